// round 13
// baseline (speedup 1.0000x reference)
#include <cuda_runtime.h>
#include <cuda_fp16.h>
#include <math.h>
#include <stdint.h>

// Problem constants
#define D_MODEL 512
#define N_HEADS 8
#define DH      64
#define D_FF    2048
#define BATCH   4
#define SEQ     2048
#define NROWS   (BATCH*SEQ)   // 8192

// ---------------------------------------------------------------------------
// Scratch (allocation-free rule). Offsets in floats; half buffers reinterpret.
// ---------------------------------------------------------------------------
__device__ __align__(256) float g_scratch[25165824];

#define OFF_XN1  0u          // half [8192][512]
#define OFF_Q    2097152u    // half [B][H][S][Dh]
#define OFF_K    4194304u    // half [B][H][S][Dh]
#define OFF_V    6291456u    // half [B][H][Dh][S]  (transposed!)
#define OFF_X1   8388608u    // float [8192][512]
#define OFF_XN2  12582912u   // half [8192][512]
#define OFF_MID  14680064u   // half [8192][2048]
#define OFF_WQKV 23068672u   // half [1536][512]  (transposed [out][in], Q|K|V)
#define OFF_W1   23461888u   // half [2048][512]
#define OFF_W2   23986176u   // half [512][2048]
#define OFF_BQKV 24510464u   // float [1536]

// ---------------------------------------------------------------------------
// Helpers
// ---------------------------------------------------------------------------
__device__ __forceinline__ void mma_f16(float* d, const uint32_t* a, const uint32_t* b) {
    asm volatile(
        "mma.sync.aligned.m16n8k16.row.col.f32.f16.f16.f32 "
        "{%0,%1,%2,%3}, {%4,%5,%6,%7}, {%8,%9}, {%0,%1,%2,%3};\n"
        : "+f"(d[0]), "+f"(d[1]), "+f"(d[2]), "+f"(d[3])
        : "r"(a[0]), "r"(a[1]), "r"(a[2]), "r"(a[3]), "r"(b[0]), "r"(b[1]));
}

__device__ __forceinline__ void ldsm_x4(uint32_t* r, uint32_t addr) {
    asm volatile("ldmatrix.sync.aligned.m8n8.x4.shared.b16 {%0,%1,%2,%3}, [%4];"
        : "=r"(r[0]), "=r"(r[1]), "=r"(r[2]), "=r"(r[3]) : "r"(addr));
}
__device__ __forceinline__ void ldsm_x2(uint32_t* r, uint32_t addr) {
    asm volatile("ldmatrix.sync.aligned.m8n8.x2.shared.b16 {%0,%1}, [%2];"
        : "=r"(r[0]), "=r"(r[1]) : "r"(addr));
}

__device__ __forceinline__ uint32_t sigmoid_h2(float z0, float z1) {
    // sigmoid(z) = 0.5 + 0.5*tanh(0.5*z); inputs are already 0.5*scale*score
    __half2 hz = __floats2half2_rn(z0, z1);
    uint32_t u = *(uint32_t*)&hz;
    uint32_t t;
    asm("tanh.approx.f16x2 %0, %1;" : "=r"(t) : "r"(u));
    __half2 th = *(__half2*)&t;
    __half2 r = __hfma2(th, __float2half2_rn(0.5f), __float2half2_rn(0.5f));
    return *(uint32_t*)&r;
}

__device__ __forceinline__ void cpasync16(uint32_t s, const void* g) {
    asm volatile("cp.async.cg.shared.global [%0], [%1], 16;" :: "r"(s), "l"(g));
}
__device__ __forceinline__ void cpcommit() { asm volatile("cp.async.commit_group;"); }
__device__ __forceinline__ void cpwait0()  { asm volatile("cp.async.wait_group 0;"); }
__device__ __forceinline__ void cpwait1()  { asm volatile("cp.async.wait_group 1;"); }

__device__ __forceinline__ uint32_t smem_u32(const void* p) {
    return (uint32_t)__cvta_generic_to_shared(p);
}

// ---------------------------------------------------------------------------
// Fused weight convert + transpose: 5 weights, one launch.
// ---------------------------------------------------------------------------
__global__ __launch_bounds__(256) void transpose_all_kernel(
    const float* __restrict__ Wq, const float* __restrict__ Wk,
    const float* __restrict__ Wv, const float* __restrict__ W1,
    const float* __restrict__ W2,
    __half* __restrict__ wqkv, __half* __restrict__ w1t, __half* __restrict__ w2t)
{
    __shared__ float t[32][33];
    int tb = blockIdx.x;
    const float* W; __half* Wt; int K, M, mcols;
    if (tb < 768) {
        int wsel = tb >> 8; tb &= 255;
        W = (wsel == 0) ? Wq : (wsel == 1) ? Wk : Wv;
        Wt = wqkv + (size_t)wsel * 262144u;
        K = 512; M = 512; mcols = 16;
    } else if (tb < 1792) {
        tb -= 768; W = W1; Wt = w1t; K = 512; M = 2048; mcols = 64;
    } else {
        tb -= 1792; W = W2; Wt = w2t; K = 2048; M = 512; mcols = 16;
    }
    int m0 = (tb % mcols) * 32, k0 = (tb / mcols) * 32;
    int tx = threadIdx.x, ty = threadIdx.y;
    #pragma unroll
    for (int j = 0; j < 4; j++) {
        int kr = ty + j * 8;
        t[kr][tx] = W[(size_t)(k0 + kr) * M + m0 + tx];
    }
    __syncthreads();
    #pragma unroll
    for (int j = 0; j < 4; j++) {
        int mr = ty + j * 8;
        Wt[(size_t)(m0 + mr) * K + k0 + tx] = __float2half(t[tx][mr]);
    }
}

// Concat three 512-float bias vectors.
__global__ __launch_bounds__(512) void concat_bias_kernel(
    const float* __restrict__ a, const float* __restrict__ b,
    const float* __restrict__ c, float* __restrict__ o)
{
    int t = threadIdx.x;
    o[t] = a[t]; o[512 + t] = b[t]; o[1024 + t] = c[t];
}

// ---------------------------------------------------------------------------
// LayerNorm: block per row, 256 threads, half output.
// ---------------------------------------------------------------------------
__global__ __launch_bounds__(256) void ln_kernel(
    const float* __restrict__ x, const float* __restrict__ g,
    const float* __restrict__ b, __half* __restrict__ y)
{
    int row = blockIdx.x;
    int t = threadIdx.x;
    const float2* xr = (const float2*)(x + (size_t)row * D_MODEL);
    __half2* yr = (__half2*)(y + (size_t)row * D_MODEL);
    float2 v = xr[t];

    __shared__ float red[8];

    float s = v.x + v.y;
    #pragma unroll
    for (int o = 16; o > 0; o >>= 1) s += __shfl_xor_sync(0xffffffffu, s, o);
    if ((t & 31) == 0) red[t >> 5] = s;
    __syncthreads();
    float tot = 0.f;
    #pragma unroll
    for (int i = 0; i < 8; i++) tot += red[i];
    float mu = tot * (1.0f / D_MODEL);
    __syncthreads();

    float d0 = v.x - mu, d1 = v.y - mu;
    s = d0 * d0 + d1 * d1;
    #pragma unroll
    for (int o = 16; o > 0; o >>= 1) s += __shfl_xor_sync(0xffffffffu, s, o);
    if ((t & 31) == 0) red[t >> 5] = s;
    __syncthreads();
    tot = 0.f;
    #pragma unroll
    for (int i = 0; i < 8; i++) tot += red[i];
    float inv = rsqrtf(tot * (1.0f / D_MODEL) + 1e-5f);

    float2 gg = ((const float2*)g)[t];
    float2 bb = ((const float2*)b)[t];
    yr[t] = __floats2half2_rn(d0 * inv * gg.x + bb.x, d1 * inv * gg.y + bb.y);
}

// ---------------------------------------------------------------------------
// FP16 tensor-core GEMM, 3-stage cp.async pipeline + ldmatrix fragments.
// 128x128x32 block tile, 256 threads (8 warps, 2x4), 64x32 warp tiles.
// Stage s=it%3; wait_group 1 at top (stage it done, it+1 in flight),
// prefetch stage it+2, compute stage it. Last iter: wait_group 0.
// ---------------------------------------------------------------------------
#define SH 40
#define GEMM_SMEM (3*(2*128*SH*2))   // 61440 B

__global__ __launch_bounds__(256, 2) void gemm_h(
    const __half* __restrict__ A, const __half* __restrict__ Wt,
    const float* __restrict__ bias, const float* __restrict__ resid,
    void* __restrict__ Cv, int K, int M, int mode)
{
    extern __shared__ __half sm[];
    __half* As = sm;                 // [3][128][SH]
    __half* Bs = sm + 3 * 128 * SH;  // [3][128][SH]

    int tid = threadIdx.x;
    int w = tid >> 5, lane = tid & 31;
    int g = lane >> 2, t4 = lane & 3;
    int wr = w >> 2, wc = w & 3;
    int rowBase = blockIdx.y * 128;
    int colBase = blockIdx.x * 128;

    uint32_t sA = smem_u32(As);
    uint32_t sB = smem_u32(Bs);

    // ldmatrix per-lane base offsets (bytes)
    uint32_t aOff = ((wr * 64 + (lane & 15)) * SH + 8 * (lane >> 4)) * 2;
    uint32_t bOff = ((wc * 32 + (lane & 7)) * SH + 8 * ((lane >> 3) & 1)) * 2;

    float acc[4][4][4];
    #pragma unroll
    for (int mf = 0; mf < 4; mf++)
        #pragma unroll
        for (int nf = 0; nf < 4; nf++)
            #pragma unroll
            for (int r = 0; r < 4; r++) acc[mf][nf][r] = 0.f;

    int rr[2], rc[2];
    #pragma unroll
    for (int j = 0; j < 2; j++) {
        int i = tid + 256 * j;
        rr[j] = i >> 2; rc[j] = (i & 3) * 8;
    }

    int nk = K >> 5;

    // Prefetch stages 0 and 1 (nk >= 16 always here).
    #pragma unroll
    for (int pf = 0; pf < 2; pf++) {
        int k0 = pf << 5;
        uint32_t ab = sA + pf * 128 * SH * 2;
        uint32_t bb = sB + pf * 128 * SH * 2;
        #pragma unroll
        for (int j = 0; j < 2; j++) {
            cpasync16(ab + (rr[j] * SH + rc[j]) * 2,
                      A + (size_t)(rowBase + rr[j]) * K + k0 + rc[j]);
            cpasync16(bb + (rr[j] * SH + rc[j]) * 2,
                      Wt + (size_t)(colBase + rr[j]) * K + k0 + rc[j]);
        }
        cpcommit();
    }

    int bc = 0, bp = 2;   // compute buf = it%3, prefetch buf = (it+2)%3
    for (int it = 0; it < nk; it++) {
        if (it == nk - 1) cpwait0(); else cpwait1();
        __syncthreads();
        if (it + 2 < nk) {
            int k0 = (it + 2) << 5;
            uint32_t ab = sA + bp * 128 * SH * 2;
            uint32_t bb = sB + bp * 128 * SH * 2;
            #pragma unroll
            for (int j = 0; j < 2; j++) {
                cpasync16(ab + (rr[j] * SH + rc[j]) * 2,
                          A + (size_t)(rowBase + rr[j]) * K + k0 + rc[j]);
                cpasync16(bb + (rr[j] * SH + rc[j]) * 2,
                          Wt + (size_t)(colBase + rr[j]) * K + k0 + rc[j]);
            }
            cpcommit();
        }
        uint32_t aB = sA + aOff + bc * 128 * SH * 2;
        uint32_t bB = sB + bOff + bc * 128 * SH * 2;

        #pragma unroll
        for (int ks = 0; ks < 32; ks += 16) {
            uint32_t a[4][4], bf[4][2];
            #pragma unroll
            for (int mf = 0; mf < 4; mf++)
                ldsm_x4(a[mf], aB + (mf * 16 * SH + ks) * 2);
            #pragma unroll
            for (int nf = 0; nf < 4; nf++)
                ldsm_x2(bf[nf], bB + (nf * 8 * SH + ks) * 2);
            #pragma unroll
            for (int mf = 0; mf < 4; mf++)
                #pragma unroll
                for (int nf = 0; nf < 4; nf++)
                    mma_f16(acc[mf][nf], a[mf], bf[nf]);
        }
        bc = (bc == 2) ? 0 : bc + 1;
        bp = (bp == 2) ? 0 : bp + 1;
    }

    // Epilogue
    #pragma unroll
    for (int mf = 0; mf < 4; mf++) {
        int r0 = rowBase + wr * 64 + mf * 16 + g;
        #pragma unroll
        for (int nf = 0; nf < 4; nf++) {
            int c0 = colBase + wc * 32 + nf * 8 + 2 * t4;
            float b0 = bias[c0], b1 = bias[c0 + 1];
            #pragma unroll
            for (int half_ = 0; half_ < 2; half_++) {
                int row = r0 + half_ * 8;
                float v0 = acc[mf][nf][half_ * 2 + 0] + b0;
                float v1 = acc[mf][nf][half_ * 2 + 1] + b1;
                if (mode == 0) {
                    int proj = c0 >> 9;
                    int cl = c0 & 511;
                    int b_ = row >> 11, s = row & 2047, h = cl >> 6, d = cl & 63;
                    __half* base = (__half*)Cv + (size_t)proj * 4194304u;
                    if (proj < 2) {
                        __half2* C = (__half2*)(base +
                            ((((size_t)b_ * N_HEADS + h) * SEQ + s) * DH + d));
                        *C = __floats2half2_rn(v0, v1);
                    } else {
                        size_t vo = (((size_t)b_ * N_HEADS + h) * DH + d) * SEQ + s;
                        base[vo] = __float2half(v0);
                        base[vo + SEQ] = __float2half(v1);
                    }
                } else if (mode == 1) {
                    __half2* C = (__half2*)((__half*)Cv + (size_t)row * M + c0);
                    *C = __floats2half2_rn(fmaxf(v0, 0.f), fmaxf(v1, 0.f));
                } else {
                    float2 rv = *(const float2*)(resid + (size_t)row * M + c0);
                    *(float2*)((float*)Cv + (size_t)row * M + c0) =
                        make_float2(v0 + rv.x, v1 + rv.y);
                }
            }
        }
    }
}

// ---------------------------------------------------------------------------
// Sigmoid-pointwise attention, fp16 tensor cores + cp.async pipelining +
// ldmatrix fragment loads. (unchanged from R8)
// ---------------------------------------------------------------------------
#define AQ 72
#define AV 136
#define ATTN_SMEM ((128*AQ + 2*128*AQ + 64*AV + 128*AV) * 2)   // 107520

__global__ __launch_bounds__(512, 2) void attn_h(
    const __half* __restrict__ q, const __half* __restrict__ kk,
    const __half* __restrict__ vv, const float* __restrict__ x,
    float* __restrict__ x1)
{
    extern __shared__ __half sm[];
    __half* Qs = sm;                     // [128][AQ]  [s][d]
    __half* Ks = Qs + 128 * AQ;          // [2][128][AQ]  [t][d]
    __half* Vs = Ks + 2 * 128 * AQ;      // [64][AV]   [d][t]
    __half* Ps = Vs + 64 * AV;           // [128][AV]  [s][t]

    int b = blockIdx.z, h = blockIdx.y;
    int s0 = blockIdx.x * 128;
    const __half* qbase = q + (((size_t)b * N_HEADS + h) * SEQ + s0) * DH;
    const __half* kbase = kk + ((size_t)b * N_HEADS + h) * SEQ * DH;
    const __half* vbase = vv + ((size_t)b * N_HEADS + h) * DH * SEQ;

    int tid = threadIdx.x, w = tid >> 5, lane = tid & 31;
    int g = lane >> 2, t4 = lane & 3;
    int wr1 = w >> 2, wc1 = w & 3;   // mm1: 4x4 grid of 32x32
    int wr2 = w >> 1, wc2 = w & 1;   // mm2: 8x2 grid of 16x32

    uint32_t qS = smem_u32(Qs);
    uint32_t kS = smem_u32(Ks);
    uint32_t vS = smem_u32(Vs);
    uint32_t pS = smem_u32(Ps);

    // ldmatrix per-lane base offsets (bytes)
    uint32_t qaOff = qS + ((wr1 * 32 + (lane & 15)) * AQ + 8 * (lane >> 4)) * 2;
    uint32_t kbOff = ((wc1 * 32 + (lane & 7)) * AQ + 8 * ((lane >> 3) & 1)) * 2;
    uint32_t paOff = pS + ((wr2 * 16 + (lane & 15)) * AV + 8 * (lane >> 4)) * 2;
    uint32_t vbOff = vS + ((wc2 * 32 + (lane & 7)) * AV + 8 * ((lane >> 3) & 1)) * 2;

    // indices for async loads (2 chunks of 16B each for K and for V)
    int kr[2], kc[2], vd[2], vc[2];
    #pragma unroll
    for (int j = 0; j < 2; j++) {
        int i = tid + 512 * j;
        kr[j] = i >> 3;  kc[j] = (i & 7) * 8;     // 128 rows x 8 chunks
        vd[j] = i >> 4;  vc[j] = (i & 15) * 8;    // 64 rows x 16 chunks
    }

    // Prologue: Q + K(0) in group A; V(0) in group B.
    #pragma unroll
    for (int j = 0; j < 2; j++) {
        cpasync16(qS + (kr[j] * AQ + kc[j]) * 2, qbase + (size_t)kr[j] * DH + kc[j]);
        cpasync16(kS + (kr[j] * AQ + kc[j]) * 2, kbase + (size_t)kr[j] * DH + kc[j]);
    }
    cpcommit();
    #pragma unroll
    for (int j = 0; j < 2; j++)
        cpasync16(vS + (vd[j] * AV + vc[j]) * 2, vbase + (size_t)vd[j] * SEQ + vc[j]);
    cpcommit();

    float o[4][4];
    #pragma unroll
    for (int nf = 0; nf < 4; nf++)
        #pragma unroll
        for (int r = 0; r < 4; r++) o[nf][r] = 0.f;

    const float hscale = 0.5f * 0.04419417382415922f;  // 0.5/sqrt(512)

    int buf = 0;
    for (int t0 = 0; t0 < SEQ; t0 += 128) {
        bool more = (t0 + 128 < SEQ);
        cpwait1();
        __syncthreads();

        // Prefetch K(t+1) into other buffer.
        if (more) {
            uint32_t kd = kS + (buf ^ 1) * 128 * AQ * 2;
            #pragma unroll
            for (int j = 0; j < 2; j++)
                cpasync16(kd + (kr[j] * AQ + kc[j]) * 2,
                          kbase + (size_t)(t0 + 128 + kr[j]) * DH + kc[j]);
            cpcommit();
        }

        uint32_t kB = kS + kbOff + buf * 128 * AQ * 2;

        // mm1: P = Q K^T
        float p[2][4][4];
        #pragma unroll
        for (int mf = 0; mf < 2; mf++)
            #pragma unroll
            for (int nf = 0; nf < 4; nf++)
                #pragma unroll
                for (int r = 0; r < 4; r++) p[mf][nf][r] = 0.f;

        #pragma unroll
        for (int ks = 0; ks < 64; ks += 16) {
            uint32_t a[2][4], bf[4][2];
            #pragma unroll
            for (int mf = 0; mf < 2; mf++)
                ldsm_x4(a[mf], qaOff + (mf * 16 * AQ + ks) * 2);
            #pragma unroll
            for (int nf = 0; nf < 4; nf++)
                ldsm_x2(bf[nf], kB + (nf * 8 * AQ + ks) * 2);
            #pragma unroll
            for (int mf = 0; mf < 2; mf++)
                #pragma unroll
                for (int nf = 0; nf < 4; nf++)
                    mma_f16(p[mf][nf], a[mf], bf[nf]);
        }

        // sigmoid via tanh.approx.f16x2 -> half2 Ps[s][t]
        #pragma unroll
        for (int mf = 0; mf < 2; mf++) {
            int r0 = wr1 * 32 + mf * 16 + g;
            #pragma unroll
            for (int nf = 0; nf < 4; nf++) {
                int c0 = wc1 * 32 + nf * 8 + 2 * t4;
                #pragma unroll
                for (int half_ = 0; half_ < 2; half_++) {
                    int rw = r0 + half_ * 8;
                    uint32_t r2 = sigmoid_h2(p[mf][nf][half_ * 2 + 0] * hscale,
                                             p[mf][nf][half_ * 2 + 1] * hscale);
                    *(uint32_t*)(Ps + rw * AV + c0) = r2;
                }
            }
        }

        if (more) cpwait1(); else cpwait0();
        __syncthreads();   // Ps + Vs visible

        // mm2: O += P V
        #pragma unroll
        for (int ks = 0; ks < 128; ks += 16) {
            uint32_t a[4], bf[4][2];
            ldsm_x4(a, paOff + ks * 2);
            #pragma unroll
            for (int nf = 0; nf < 4; nf++)
                ldsm_x2(bf[nf], vbOff + (nf * 8 * AV + ks) * 2);
            #pragma unroll
            for (int nf = 0; nf < 4; nf++)
                mma_f16(o[nf], a, bf[nf]);
        }

        __syncthreads();   // everyone done reading Vs (and Ps)

        // Issue V(t+1); completes during next tile's mm1.
        if (more) {
            #pragma unroll
            for (int j = 0; j < 2; j++)
                cpasync16(vS + (vd[j] * AV + vc[j]) * 2,
                          vbase + (size_t)vd[j] * SEQ + t0 + 128 + vc[j]);
            cpcommit();
        }
        buf ^= 1;
    }

    // Epilogue: x1 = x + O
    int r0 = wr2 * 16 + g;
    #pragma unroll
    for (int nf = 0; nf < 4; nf++) {
        int col = h * DH + wc2 * 32 + nf * 8 + 2 * t4;
        #pragma unroll
        for (int half_ = 0; half_ < 2; half_++) {
            int s = s0 + r0 + half_ * 8;
            size_t idx = ((size_t)(b * SEQ + s)) * D_MODEL + col;
            float2 xr = *(const float2*)(x + idx);
            *(float2*)(x1 + idx) = make_float2(xr.x + o[nf][half_ * 2 + 0],
                                               xr.y + o[nf][half_ * 2 + 1]);
        }
    }
}

// ---------------------------------------------------------------------------
// kernel_launch
// ---------------------------------------------------------------------------
extern "C" void kernel_launch(void* const* d_in, const int* in_sizes, int n_in,
                              void* d_out, int out_size)
{
    (void)in_sizes; (void)n_in; (void)out_size;
    const float* x   = (const float*)d_in[0];
    const float* Wq  = (const float*)d_in[1];
    const float* bq  = (const float*)d_in[2];
    const float* Wk  = (const float*)d_in[3];
    const float* bk  = (const float*)d_in[4];
    const float* Wv  = (const float*)d_in[5];
    const float* bv  = (const float*)d_in[6];
    const float* W1  = (const float*)d_in[7];
    const float* b1  = (const float*)d_in[8];
    const float* W2  = (const float*)d_in[9];
    const float* b2  = (const float*)d_in[10];
    const float* g1  = (const float*)d_in[11];
    const float* be1 = (const float*)d_in[12];
    const float* g2  = (const float*)d_in[13];
    const float* be2 = (const float*)d_in[14];
    float* out = (float*)d_out;

    float* scratch = nullptr;
    cudaGetSymbolAddress((void**)&scratch, g_scratch);
    __half* xn1 = (__half*)(scratch + OFF_XN1);
    __half* qb  = (__half*)(scratch + OFF_Q);
    __half* kb  = (__half*)(scratch + OFF_K);
    __half* vb  = (__half*)(scratch + OFF_V);
    float*  x1  = scratch + OFF_X1;
    __half* xn2 = (__half*)(scratch + OFF_XN2);
    __half* mid = (__half*)(scratch + OFF_MID);
    __half* wqkv = (__half*)(scratch + OFF_WQKV);
    __half* w1t = (__half*)(scratch + OFF_W1);
    __half* w2t = (__half*)(scratch + OFF_W2);
    float*  bqkv = scratch + OFF_BQKV;

    cudaFuncSetAttribute(gemm_h, cudaFuncAttributeMaxDynamicSharedMemorySize, GEMM_SMEM);
    cudaFuncSetAttribute(attn_h, cudaFuncAttributeMaxDynamicSharedMemorySize, ATTN_SMEM);

    // Fused weight transpose/convert (one launch) + bias concat.
    transpose_all_kernel<<<2816, dim3(32, 8)>>>(Wq, Wk, Wv, W1, W2, wqkv, w1t, w2t);
    concat_bias_kernel<<<1, 512>>>(bq, bk, bv, bqkv);

    // LN1 -> half
    ln_kernel<<<NROWS, 256>>>(x, g1, be1, xn1);
    // Fused QKV projection (Q,K: [B,H,S,Dh]; V: [B,H,Dh,S])
    gemm_h<<<dim3(12, 64), 256, GEMM_SMEM>>>(xn1, wqkv, bqkv, nullptr, qb, 512, 1536, 0);
    // Sigmoid attention + residual -> x1 (fp32)
    attn_h<<<dim3(16, 8, 4), 512, ATTN_SMEM>>>(qb, kb, vb, x, x1);
    // LN2 -> half
    ln_kernel<<<NROWS, 256>>>(x1, g2, be2, xn2);
    // FFN
    gemm_h<<<dim3(16, 64), 256, GEMM_SMEM>>>(xn2, w1t, b1, nullptr, mid, 512, 2048, 1);
    gemm_h<<<dim3(4, 64), 256, GEMM_SMEM>>>(mid, w2t, b2, x1, out, 2048, 512, 2);
}

// round 14
// speedup vs baseline: 1.0524x; 1.0524x over previous
#include <cuda_runtime.h>
#include <cuda_fp16.h>
#include <math.h>
#include <stdint.h>

// Problem constants
#define D_MODEL 512
#define N_HEADS 8
#define DH      64
#define D_FF    2048
#define BATCH   4
#define SEQ     2048
#define NROWS   (BATCH*SEQ)   // 8192

// ---------------------------------------------------------------------------
// Scratch (allocation-free rule). Offsets in floats; half buffers reinterpret.
// ---------------------------------------------------------------------------
__device__ __align__(256) float g_scratch[25165824];

#define OFF_XN1  0u          // half [8192][512]
#define OFF_Q    2097152u    // half [B][H][S][Dh]
#define OFF_K    4194304u    // half [B][H][S][Dh]
#define OFF_V    6291456u    // half [B][H][Dh][S]  (transposed!)
#define OFF_X1   8388608u    // float [8192][512]
#define OFF_XN2  12582912u   // half [8192][512]
#define OFF_MID  14680064u   // half [8192][2048]
#define OFF_WQKV 23068672u   // half [1536][512]  (transposed [out][in], Q|K|V)
#define OFF_W1   23461888u   // half [2048][512]
#define OFF_W2   23986176u   // half [512][2048]
#define OFF_BQKV 24510464u   // float [1536]

// ---------------------------------------------------------------------------
// Helpers
// ---------------------------------------------------------------------------
__device__ __forceinline__ void mma_f16(float* d, const uint32_t* a, const uint32_t* b) {
    asm volatile(
        "mma.sync.aligned.m16n8k16.row.col.f32.f16.f16.f32 "
        "{%0,%1,%2,%3}, {%4,%5,%6,%7}, {%8,%9}, {%0,%1,%2,%3};\n"
        : "+f"(d[0]), "+f"(d[1]), "+f"(d[2]), "+f"(d[3])
        : "r"(a[0]), "r"(a[1]), "r"(a[2]), "r"(a[3]), "r"(b[0]), "r"(b[1]));
}

__device__ __forceinline__ void ldsm_x4(uint32_t* r, uint32_t addr) {
    asm volatile("ldmatrix.sync.aligned.m8n8.x4.shared.b16 {%0,%1,%2,%3}, [%4];"
        : "=r"(r[0]), "=r"(r[1]), "=r"(r[2]), "=r"(r[3]) : "r"(addr));
}
__device__ __forceinline__ void ldsm_x2(uint32_t* r, uint32_t addr) {
    asm volatile("ldmatrix.sync.aligned.m8n8.x2.shared.b16 {%0,%1}, [%2];"
        : "=r"(r[0]), "=r"(r[1]) : "r"(addr));
}

__device__ __forceinline__ uint32_t sigmoid_h2(float z0, float z1) {
    // sigmoid(z) = 0.5 + 0.5*tanh(0.5*z); inputs are already 0.5*scale*score
    __half2 hz = __floats2half2_rn(z0, z1);
    uint32_t u = *(uint32_t*)&hz;
    uint32_t t;
    asm("tanh.approx.f16x2 %0, %1;" : "=r"(t) : "r"(u));
    __half2 th = *(__half2*)&t;
    __half2 r = __hfma2(th, __float2half2_rn(0.5f), __float2half2_rn(0.5f));
    return *(uint32_t*)&r;
}

__device__ __forceinline__ void cpasync16(uint32_t s, const void* g) {
    asm volatile("cp.async.cg.shared.global [%0], [%1], 16;" :: "r"(s), "l"(g));
}
__device__ __forceinline__ void cpcommit() { asm volatile("cp.async.commit_group;"); }
__device__ __forceinline__ void cpwait0()  { asm volatile("cp.async.wait_group 0;"); }
__device__ __forceinline__ void cpwait1()  { asm volatile("cp.async.wait_group 1;"); }

__device__ __forceinline__ uint32_t smem_u32(const void* p) {
    return (uint32_t)__cvta_generic_to_shared(p);
}

// ---------------------------------------------------------------------------
// Fused weight convert + transpose: 5 weights, one launch.
// ---------------------------------------------------------------------------
__global__ __launch_bounds__(256) void transpose_all_kernel(
    const float* __restrict__ Wq, const float* __restrict__ Wk,
    const float* __restrict__ Wv, const float* __restrict__ W1,
    const float* __restrict__ W2,
    __half* __restrict__ wqkv, __half* __restrict__ w1t, __half* __restrict__ w2t)
{
    __shared__ float t[32][33];
    int tb = blockIdx.x;
    const float* W; __half* Wt; int K, M, mcols;
    if (tb < 768) {
        int wsel = tb >> 8; tb &= 255;
        W = (wsel == 0) ? Wq : (wsel == 1) ? Wk : Wv;
        Wt = wqkv + (size_t)wsel * 262144u;
        K = 512; M = 512; mcols = 16;
    } else if (tb < 1792) {
        tb -= 768; W = W1; Wt = w1t; K = 512; M = 2048; mcols = 64;
    } else {
        tb -= 1792; W = W2; Wt = w2t; K = 2048; M = 512; mcols = 16;
    }
    int m0 = (tb % mcols) * 32, k0 = (tb / mcols) * 32;
    int tx = threadIdx.x, ty = threadIdx.y;
    #pragma unroll
    for (int j = 0; j < 4; j++) {
        int kr = ty + j * 8;
        t[kr][tx] = W[(size_t)(k0 + kr) * M + m0 + tx];
    }
    __syncthreads();
    #pragma unroll
    for (int j = 0; j < 4; j++) {
        int mr = ty + j * 8;
        Wt[(size_t)(m0 + mr) * K + k0 + tx] = __float2half(t[tx][mr]);
    }
}

// Concat three 512-float bias vectors.
__global__ __launch_bounds__(512) void concat_bias_kernel(
    const float* __restrict__ a, const float* __restrict__ b,
    const float* __restrict__ c, float* __restrict__ o)
{
    int t = threadIdx.x;
    o[t] = a[t]; o[512 + t] = b[t]; o[1024 + t] = c[t];
}

// ---------------------------------------------------------------------------
// LayerNorm: block per row, 256 threads, half output.
// ---------------------------------------------------------------------------
__global__ __launch_bounds__(256) void ln_kernel(
    const float* __restrict__ x, const float* __restrict__ g,
    const float* __restrict__ b, __half* __restrict__ y)
{
    int row = blockIdx.x;
    int t = threadIdx.x;
    const float2* xr = (const float2*)(x + (size_t)row * D_MODEL);
    __half2* yr = (__half2*)(y + (size_t)row * D_MODEL);
    float2 v = xr[t];

    __shared__ float red[8];

    float s = v.x + v.y;
    #pragma unroll
    for (int o = 16; o > 0; o >>= 1) s += __shfl_xor_sync(0xffffffffu, s, o);
    if ((t & 31) == 0) red[t >> 5] = s;
    __syncthreads();
    float tot = 0.f;
    #pragma unroll
    for (int i = 0; i < 8; i++) tot += red[i];
    float mu = tot * (1.0f / D_MODEL);
    __syncthreads();

    float d0 = v.x - mu, d1 = v.y - mu;
    s = d0 * d0 + d1 * d1;
    #pragma unroll
    for (int o = 16; o > 0; o >>= 1) s += __shfl_xor_sync(0xffffffffu, s, o);
    if ((t & 31) == 0) red[t >> 5] = s;
    __syncthreads();
    tot = 0.f;
    #pragma unroll
    for (int i = 0; i < 8; i++) tot += red[i];
    float inv = rsqrtf(tot * (1.0f / D_MODEL) + 1e-5f);

    float2 gg = ((const float2*)g)[t];
    float2 bb = ((const float2*)b)[t];
    yr[t] = __floats2half2_rn(d0 * inv * gg.x + bb.x, d1 * inv * gg.y + bb.y);
}

// ---------------------------------------------------------------------------
// FP16 tensor-core GEMM, 3-stage cp.async pipeline + ldmatrix fragments.
// (unchanged from R11)
// ---------------------------------------------------------------------------
#define SH 40
#define GEMM_SMEM (3*(2*128*SH*2))   // 61440 B

__global__ __launch_bounds__(256, 2) void gemm_h(
    const __half* __restrict__ A, const __half* __restrict__ Wt,
    const float* __restrict__ bias, const float* __restrict__ resid,
    void* __restrict__ Cv, int K, int M, int mode)
{
    extern __shared__ __half sm[];
    __half* As = sm;                 // [3][128][SH]
    __half* Bs = sm + 3 * 128 * SH;  // [3][128][SH]

    int tid = threadIdx.x;
    int w = tid >> 5, lane = tid & 31;
    int g = lane >> 2, t4 = lane & 3;
    int wr = w >> 2, wc = w & 3;
    int rowBase = blockIdx.y * 128;
    int colBase = blockIdx.x * 128;

    uint32_t sA = smem_u32(As);
    uint32_t sB = smem_u32(Bs);

    uint32_t aOff = ((wr * 64 + (lane & 15)) * SH + 8 * (lane >> 4)) * 2;
    uint32_t bOff = ((wc * 32 + (lane & 7)) * SH + 8 * ((lane >> 3) & 1)) * 2;

    float acc[4][4][4];
    #pragma unroll
    for (int mf = 0; mf < 4; mf++)
        #pragma unroll
        for (int nf = 0; nf < 4; nf++)
            #pragma unroll
            for (int r = 0; r < 4; r++) acc[mf][nf][r] = 0.f;

    int rr[2], rc[2];
    #pragma unroll
    for (int j = 0; j < 2; j++) {
        int i = tid + 256 * j;
        rr[j] = i >> 2; rc[j] = (i & 3) * 8;
    }

    int nk = K >> 5;

    #pragma unroll
    for (int pf = 0; pf < 2; pf++) {
        int k0 = pf << 5;
        uint32_t ab = sA + pf * 128 * SH * 2;
        uint32_t bb = sB + pf * 128 * SH * 2;
        #pragma unroll
        for (int j = 0; j < 2; j++) {
            cpasync16(ab + (rr[j] * SH + rc[j]) * 2,
                      A + (size_t)(rowBase + rr[j]) * K + k0 + rc[j]);
            cpasync16(bb + (rr[j] * SH + rc[j]) * 2,
                      Wt + (size_t)(colBase + rr[j]) * K + k0 + rc[j]);
        }
        cpcommit();
    }

    int bc = 0, bp = 2;
    for (int it = 0; it < nk; it++) {
        if (it == nk - 1) cpwait0(); else cpwait1();
        __syncthreads();
        if (it + 2 < nk) {
            int k0 = (it + 2) << 5;
            uint32_t ab = sA + bp * 128 * SH * 2;
            uint32_t bb = sB + bp * 128 * SH * 2;
            #pragma unroll
            for (int j = 0; j < 2; j++) {
                cpasync16(ab + (rr[j] * SH + rc[j]) * 2,
                          A + (size_t)(rowBase + rr[j]) * K + k0 + rc[j]);
                cpasync16(bb + (rr[j] * SH + rc[j]) * 2,
                          Wt + (size_t)(colBase + rr[j]) * K + k0 + rc[j]);
            }
            cpcommit();
        }
        uint32_t aB = sA + aOff + bc * 128 * SH * 2;
        uint32_t bB = sB + bOff + bc * 128 * SH * 2;

        #pragma unroll
        for (int ks = 0; ks < 32; ks += 16) {
            uint32_t a[4][4], bf[4][2];
            #pragma unroll
            for (int mf = 0; mf < 4; mf++)
                ldsm_x4(a[mf], aB + (mf * 16 * SH + ks) * 2);
            #pragma unroll
            for (int nf = 0; nf < 4; nf++)
                ldsm_x2(bf[nf], bB + (nf * 8 * SH + ks) * 2);
            #pragma unroll
            for (int mf = 0; mf < 4; mf++)
                #pragma unroll
                for (int nf = 0; nf < 4; nf++)
                    mma_f16(acc[mf][nf], a[mf], bf[nf]);
        }
        bc = (bc == 2) ? 0 : bc + 1;
        bp = (bp == 2) ? 0 : bp + 1;
    }

    // Epilogue
    #pragma unroll
    for (int mf = 0; mf < 4; mf++) {
        int r0 = rowBase + wr * 64 + mf * 16 + g;
        #pragma unroll
        for (int nf = 0; nf < 4; nf++) {
            int c0 = colBase + wc * 32 + nf * 8 + 2 * t4;
            float b0 = bias[c0], b1 = bias[c0 + 1];
            #pragma unroll
            for (int half_ = 0; half_ < 2; half_++) {
                int row = r0 + half_ * 8;
                float v0 = acc[mf][nf][half_ * 2 + 0] + b0;
                float v1 = acc[mf][nf][half_ * 2 + 1] + b1;
                if (mode == 0) {
                    int proj = c0 >> 9;
                    int cl = c0 & 511;
                    int b_ = row >> 11, s = row & 2047, h = cl >> 6, d = cl & 63;
                    __half* base = (__half*)Cv + (size_t)proj * 4194304u;
                    if (proj < 2) {
                        __half2* C = (__half2*)(base +
                            ((((size_t)b_ * N_HEADS + h) * SEQ + s) * DH + d));
                        *C = __floats2half2_rn(v0, v1);
                    } else {
                        size_t vo = (((size_t)b_ * N_HEADS + h) * DH + d) * SEQ + s;
                        base[vo] = __float2half(v0);
                        base[vo + SEQ] = __float2half(v1);
                    }
                } else if (mode == 1) {
                    __half2* C = (__half2*)((__half*)Cv + (size_t)row * M + c0);
                    *C = __floats2half2_rn(fmaxf(v0, 0.f), fmaxf(v1, 0.f));
                } else {
                    float2 rv = *(const float2*)(resid + (size_t)row * M + c0);
                    *(float2*)((float*)Cv + (size_t)row * M + c0) =
                        make_float2(v0 + rv.x, v1 + rv.y);
                }
            }
        }
    }
}

// ---------------------------------------------------------------------------
// Sigmoid attention v2: 256 threads (8 warps), 64-row q-tiles, 2 CTAs/SM,
// <=128 regs (no spills). Q fragments persistent in registers.
// mm1: warp grid 2x4 (32x32 tiles), Q from regs, K via merged ldsm_x4.
// mm2: warp grid 4x2 (16x32 tiles), V redundancy 4x (was 8x).
// K double-buffered cp.async; V single-buffered overlapping mm1(t+1).
// Smem: Qs[64][AQ] Ks[2][128][AQ] Vs[64][AV] Ps[64][AV] = 80896 B.
// ---------------------------------------------------------------------------
#define AQ 72
#define AV 136
#define ATTN_SMEM ((64*AQ + 2*128*AQ + 64*AV + 64*AV) * 2)   // 80896

__global__ __launch_bounds__(256, 2) void attn_h(
    const __half* __restrict__ q, const __half* __restrict__ kk,
    const __half* __restrict__ vv, const float* __restrict__ x,
    float* __restrict__ x1)
{
    extern __shared__ __half sm[];
    __half* Qs = sm;                     // [64][AQ]   [s][d]
    __half* Ks = Qs + 64 * AQ;           // [2][128][AQ] [t][d]
    __half* Vs = Ks + 2 * 128 * AQ;      // [64][AV]   [d][t]
    __half* Ps = Vs + 64 * AV;           // [64][AV]   [s][t]

    int b = blockIdx.z, h = blockIdx.y;
    int s0 = blockIdx.x * 64;
    const __half* qbase = q + (((size_t)b * N_HEADS + h) * SEQ + s0) * DH;
    const __half* kbase = kk + ((size_t)b * N_HEADS + h) * SEQ * DH;
    const __half* vbase = vv + ((size_t)b * N_HEADS + h) * DH * SEQ;

    int tid = threadIdx.x, w = tid >> 5, lane = tid & 31;
    int g = lane >> 2, t4 = lane & 3;
    int wr1 = w >> 2, wc1 = w & 3;   // mm1: 2x4 grid, 32x32 warp tiles
    int wr2 = w >> 1, wc2 = w & 1;   // mm2: 4x2 grid, 16x32 warp tiles

    uint32_t qS = smem_u32(Qs);
    uint32_t kS = smem_u32(Ks);
    uint32_t vS = smem_u32(Vs);
    uint32_t pS = smem_u32(Ps);

    // ldmatrix per-lane addresses
    // A-type (x4, 16 rows x 16 halves): row=(lane&15), half-block=(lane>>4)
    uint32_t qaOff = qS + ((wr1 * 32 + (lane & 15)) * AQ + 8 * (lane >> 4)) * 2;
    uint32_t paOff = pS + ((wr2 * 16 + (lane & 15)) * AV + 8 * (lane >> 4)) * 2;
    // B-type merged (x4, 16 n-rows x 16 k-halves):
    // row=(lane&7)+8*(lane>>4), k-half=((lane>>3)&1)
    uint32_t kbOff = (((lane & 7) + 8 * (lane >> 4)) * AQ + 8 * ((lane >> 3) & 1)) * 2
                     + (wc1 * 32) * AQ * 2;
    uint32_t vbOff = vS + ((wc2 * 32 + (lane & 7) + 8 * (lane >> 4)) * AV
                     + 8 * ((lane >> 3) & 1)) * 2;

    // cp.async staging indices
    int kr[4], kc[4];   // K tile: 128 rows x 8 chunks (16B)
    #pragma unroll
    for (int j = 0; j < 4; j++) {
        int i = tid + 256 * j;
        kr[j] = i >> 3; kc[j] = (i & 7) * 8;
    }
    int vd[4], vc[4];   // V tile: 64 rows x 16 chunks
    #pragma unroll
    for (int j = 0; j < 4; j++) {
        int i = tid + 256 * j;
        vd[j] = i >> 4; vc[j] = (i & 15) * 8;
    }
    int qr0 = tid >> 3, qc0 = (tid & 7) * 8;   // Q tile: 64 rows x 8 chunks (512, 2/thr)

    // Prologue: [Q + K(0)] group, then [V(0)] group.
    #pragma unroll
    for (int j = 0; j < 2; j++) {
        int r = qr0 + j * 32;
        cpasync16(qS + (r * AQ + qc0) * 2, qbase + (size_t)r * DH + qc0);
    }
    #pragma unroll
    for (int j = 0; j < 4; j++)
        cpasync16(kS + (kr[j] * AQ + kc[j]) * 2, kbase + (size_t)kr[j] * DH + kc[j]);
    cpcommit();
    #pragma unroll
    for (int j = 0; j < 4; j++)
        cpasync16(vS + (vd[j] * AV + vc[j]) * 2, vbase + (size_t)vd[j] * SEQ + vc[j]);
    cpcommit();

    uint32_t qf[2][4][4];   // persistent Q fragments: [mf][kstep][4]
    float o[4][4];
    #pragma unroll
    for (int nf = 0; nf < 4; nf++)
        #pragma unroll
        for (int r = 0; r < 4; r++) o[nf][r] = 0.f;

    const float hscale = 0.5f * 0.04419417382415922f;  // 0.5/sqrt(512)

    int buf = 0;
    for (int t0 = 0; t0 < SEQ; t0 += 128) {
        bool more = (t0 + 128 < SEQ);
        cpwait1();            // K(t) (and Q on iter 0) ready
        __syncthreads();

        if (t0 == 0) {        // hoist Q fragments into registers, once
            #pragma unroll
            for (int mf = 0; mf < 2; mf++)
                #pragma unroll
                for (int ks = 0; ks < 4; ks++)
                    ldsm_x4(qf[mf][ks], qaOff + (mf * 16 * AQ + ks * 16) * 2);
        }

        // Prefetch K(t+1)
        if (more) {
            uint32_t kd = kS + (buf ^ 1) * 128 * AQ * 2;
            #pragma unroll
            for (int j = 0; j < 4; j++)
                cpasync16(kd + (kr[j] * AQ + kc[j]) * 2,
                          kbase + (size_t)(t0 + 128 + kr[j]) * DH + kc[j]);
            cpcommit();
        }

        uint32_t kB = kS + kbOff + buf * 128 * AQ * 2;

        // mm1: P[64,128] = Q K^T
        float p[2][4][4];
        #pragma unroll
        for (int mf = 0; mf < 2; mf++)
            #pragma unroll
            for (int nf = 0; nf < 4; nf++)
                #pragma unroll
                for (int r = 0; r < 4; r++) p[mf][nf][r] = 0.f;

        #pragma unroll
        for (int ks = 0; ks < 4; ks++) {
            uint32_t bf[2][4];   // two nf-pairs
            #pragma unroll
            for (int pr = 0; pr < 2; pr++)
                ldsm_x4(bf[pr], kB + (pr * 16 * AQ + ks * 16) * 2);
            #pragma unroll
            for (int mf = 0; mf < 2; mf++)
                #pragma unroll
                for (int pr = 0; pr < 2; pr++) {
                    mma_f16(p[mf][pr * 2 + 0], qf[mf][ks], bf[pr] + 0);
                    mma_f16(p[mf][pr * 2 + 1], qf[mf][ks], bf[pr] + 2);
                }
        }

        // sigmoid -> half2 Ps[s][t]
        #pragma unroll
        for (int mf = 0; mf < 2; mf++) {
            int r0 = wr1 * 32 + mf * 16 + g;
            #pragma unroll
            for (int nf = 0; nf < 4; nf++) {
                int c0 = wc1 * 32 + nf * 8 + 2 * t4;
                #pragma unroll
                for (int half_ = 0; half_ < 2; half_++) {
                    int rw = r0 + half_ * 8;
                    uint32_t r2 = sigmoid_h2(p[mf][nf][half_ * 2 + 0] * hscale,
                                             p[mf][nf][half_ * 2 + 1] * hscale);
                    *(uint32_t*)(Ps + rw * AV + c0) = r2;
                }
            }
        }

        if (more) cpwait1(); else cpwait0();   // V(t) ready
        __syncthreads();                        // Ps + Vs visible

        // mm2: O[64,64] += P V
        #pragma unroll
        for (int ks = 0; ks < 8; ks++) {
            uint32_t a[4], bf[2][4];
            ldsm_x4(a, paOff + ks * 32);        // ks*16 halves = ks*32 bytes
            #pragma unroll
            for (int pr = 0; pr < 2; pr++)
                ldsm_x4(bf[pr], vbOff + (pr * 16 * AV) * 2 + ks * 32);
            #pragma unroll
            for (int pr = 0; pr < 2; pr++) {
                mma_f16(o[pr * 2 + 0], a, bf[pr] + 0);
                mma_f16(o[pr * 2 + 1], a, bf[pr] + 2);
            }
        }

        __syncthreads();   // all reads of Vs/Ps done

        // Issue V(t+1); completes during next tile's mm1.
        if (more) {
            #pragma unroll
            for (int j = 0; j < 4; j++)
                cpasync16(vS + (vd[j] * AV + vc[j]) * 2,
                          vbase + (size_t)vd[j] * SEQ + t0 + 128 + vc[j]);
            cpcommit();
        }
        buf ^= 1;
    }

    // Epilogue: x1 = x + O
    int r0 = wr2 * 16 + g;
    #pragma unroll
    for (int nf = 0; nf < 4; nf++) {
        int col = h * DH + wc2 * 32 + nf * 8 + 2 * t4;
        #pragma unroll
        for (int half_ = 0; half_ < 2; half_++) {
            int s = s0 + r0 + half_ * 8;
            size_t idx = ((size_t)(b * SEQ + s)) * D_MODEL + col;
            float2 xr = *(const float2*)(x + idx);
            *(float2*)(x1 + idx) = make_float2(xr.x + o[nf][half_ * 2 + 0],
                                               xr.y + o[nf][half_ * 2 + 1]);
        }
    }
}

// ---------------------------------------------------------------------------
// kernel_launch
// ---------------------------------------------------------------------------
extern "C" void kernel_launch(void* const* d_in, const int* in_sizes, int n_in,
                              void* d_out, int out_size)
{
    (void)in_sizes; (void)n_in; (void)out_size;
    const float* x   = (const float*)d_in[0];
    const float* Wq  = (const float*)d_in[1];
    const float* bq  = (const float*)d_in[2];
    const float* Wk  = (const float*)d_in[3];
    const float* bk  = (const float*)d_in[4];
    const float* Wv  = (const float*)d_in[5];
    const float* bv  = (const float*)d_in[6];
    const float* W1  = (const float*)d_in[7];
    const float* b1  = (const float*)d_in[8];
    const float* W2  = (const float*)d_in[9];
    const float* b2  = (const float*)d_in[10];
    const float* g1  = (const float*)d_in[11];
    const float* be1 = (const float*)d_in[12];
    const float* g2  = (const float*)d_in[13];
    const float* be2 = (const float*)d_in[14];
    float* out = (float*)d_out;

    float* scratch = nullptr;
    cudaGetSymbolAddress((void**)&scratch, g_scratch);
    __half* xn1 = (__half*)(scratch + OFF_XN1);
    __half* qb  = (__half*)(scratch + OFF_Q);
    __half* kb  = (__half*)(scratch + OFF_K);
    __half* vb  = (__half*)(scratch + OFF_V);
    float*  x1  = scratch + OFF_X1;
    __half* xn2 = (__half*)(scratch + OFF_XN2);
    __half* mid = (__half*)(scratch + OFF_MID);
    __half* wqkv = (__half*)(scratch + OFF_WQKV);
    __half* w1t = (__half*)(scratch + OFF_W1);
    __half* w2t = (__half*)(scratch + OFF_W2);
    float*  bqkv = scratch + OFF_BQKV;

    cudaFuncSetAttribute(gemm_h, cudaFuncAttributeMaxDynamicSharedMemorySize, GEMM_SMEM);
    cudaFuncSetAttribute(attn_h, cudaFuncAttributeMaxDynamicSharedMemorySize, ATTN_SMEM);

    // Fused weight transpose/convert (one launch) + bias concat.
    transpose_all_kernel<<<2816, dim3(32, 8)>>>(Wq, Wk, Wv, W1, W2, wqkv, w1t, w2t);
    concat_bias_kernel<<<1, 512>>>(bq, bk, bv, bqkv);

    // LN1 -> half
    ln_kernel<<<NROWS, 256>>>(x, g1, be1, xn1);
    // Fused QKV projection (Q,K: [B,H,S,Dh]; V: [B,H,Dh,S])
    gemm_h<<<dim3(12, 64), 256, GEMM_SMEM>>>(xn1, wqkv, bqkv, nullptr, qb, 512, 1536, 0);
    // Sigmoid attention + residual -> x1 (fp32)
    attn_h<<<dim3(32, 8, 4), 256, ATTN_SMEM>>>(qb, kb, vb, x, x1);
    // LN2 -> half
    ln_kernel<<<NROWS, 256>>>(x1, g2, be2, xn2);
    // FFN
    gemm_h<<<dim3(16, 64), 256, GEMM_SMEM>>>(xn2, w1t, b1, nullptr, mid, 512, 2048, 1);
    gemm_h<<<dim3(4, 64), 256, GEMM_SMEM>>>(mid, w2t, b2, x1, out, 2048, 512, 2);
}